// round 1
// baseline (speedup 1.0000x reference)
#include <cuda_runtime.h>
#include <math.h>
#include <stdint.h>

#define S_   128
#define Bz   32
#define DIN  256
#define DBERT 768
#define H_   512
#define D0_  1024
#define NDJ  4096   // 2 dirs * 4H
#define NTP  32
#define NTM  64

// ---------------- persistent device scratch (static, no allocations) ----------------
__device__ float d_preG[(size_t)S_ * Bz * NDJ];   // 64 MB, pre-activation gates, reused per layer
__device__ float d_out0[(size_t)S_ * Bz * 2 * H_]; // 16 MB layer-0 output
__device__ float d_out1[(size_t)S_ * Bz * 2 * H_]; // 16 MB layer-1 output
__device__ float d_bertbias[Bz * NDJ];             // per-(b,dj) bias for layer 0
__device__ float d_hA[2 * Bz * H_];
__device__ float d_hB[2 * Bz * H_];
__device__ float d_cS[2 * Bz * H_];
__device__ float d_feat[(size_t)S_ * Bz * 96];     // [S,B,96]: cols 0..31 pos, 32..95 morph

__device__ __forceinline__ float sigmoidf_(float x) { return 1.f / (1.f + expf(-x)); }

// ---------------- zero kernel ----------------
__global__ void zero_kernel(float* out, int zero_out) {
    int i = blockIdx.x * blockDim.x + threadIdx.x;
    if (i < 2 * Bz * H_) { d_hA[i] = 0.f; d_cS[i] = 0.f; }
    if (zero_out && i == 0) out[0] = 0.f;
}

// ---------------- bert bias: bias0[b][dj] = b_ih0[dj]+b_hh0[dj] + bert[b] . W_ih0[dj, 256:1024] ----
#define BB_SMEM (32 * 772 * 4)
__global__ __launch_bounds__(256) void bert_bias_kernel(
    const float* __restrict__ bert, const float* __restrict__ w_ih0,
    const float* __restrict__ b_ih0, const float* __restrict__ b_hh0)
{
    extern __shared__ float sh[];   // bert_sh[32][772]
    const int tid = threadIdx.x;
    for (int idx = tid; idx < Bz * DBERT / 4; idx += 256) {
        float4 v = ((const float4*)bert)[idx];
        int e = idx * 4;
        int b = e / DBERT, k = e % DBERT;
        *(float4*)&sh[b * 772 + k] = v;
    }
    __syncthreads();
    const int djl = tid & 63, bq = tid >> 6;
    const int dj = blockIdx.x * 64 + djl;
    const float* wrow = w_ih0 + (size_t)dj * D0_ + DIN;
    float acc[8];
#pragma unroll
    for (int i = 0; i < 8; i++) acc[i] = 0.f;
    for (int k = 0; k < DBERT; k += 4) {
        float4 w4 = *(const float4*)&wrow[k];
#pragma unroll
        for (int i = 0; i < 8; i++) {
            int b = bq * 8 + i;
            float4 h4 = *(const float4*)&sh[b * 772 + k];
            acc[i] += w4.x * h4.x + w4.y * h4.y + w4.z * h4.z + w4.w * h4.w;
        }
    }
    float bias = b_ih0[dj] + b_hh0[dj];
#pragma unroll
    for (int i = 0; i < 8; i++)
        d_bertbias[(bq * 8 + i) * NDJ + dj] = acc[i] + bias;
}

// ---------------- tiled fp32 GEMM: C[m][n] = A[m]*W[n] (+bias), both K-major ----------------
// C is always d_preG [4096 x 4096]. A==nullptr -> use d_out0.
__global__ __launch_bounds__(256) void gemm_nt_kernel(
    const float* __restrict__ A, int lda,
    const float* __restrict__ W, int ldw,
    int K, int use_bertbias,
    const float* __restrict__ b1, const float* __restrict__ b2)
{
    __shared__ float As[16][68];
    __shared__ float Ws[16][68];
    const float* Ap = A ? A : (const float*)d_out0;
    const int tid = threadIdx.x;
    const int m0 = blockIdx.y * 64, n0 = blockIdx.x * 64;
    const int lr = tid >> 2;           // 0..63
    const int lk = (tid & 3) * 4;      // 0,4,8,12
    const int ty = tid >> 4, tx = tid & 15;
    float acc[4][4];
#pragma unroll
    for (int i = 0; i < 4; i++)
#pragma unroll
        for (int j = 0; j < 4; j++) acc[i][j] = 0.f;

    for (int k0 = 0; k0 < K; k0 += 16) {
        float4 a4 = *(const float4*)&Ap[(size_t)(m0 + lr) * lda + k0 + lk];
        float4 w4 = *(const float4*)&W[(size_t)(n0 + lr) * ldw + k0 + lk];
        As[lk + 0][lr] = a4.x; As[lk + 1][lr] = a4.y; As[lk + 2][lr] = a4.z; As[lk + 3][lr] = a4.w;
        Ws[lk + 0][lr] = w4.x; Ws[lk + 1][lr] = w4.y; Ws[lk + 2][lr] = w4.z; Ws[lk + 3][lr] = w4.w;
        __syncthreads();
#pragma unroll
        for (int kk = 0; kk < 16; kk++) {
            float4 av = *(const float4*)&As[kk][ty * 4];
            float4 wv = *(const float4*)&Ws[kk][tx * 4];
            acc[0][0] += av.x * wv.x; acc[0][1] += av.x * wv.y; acc[0][2] += av.x * wv.z; acc[0][3] += av.x * wv.w;
            acc[1][0] += av.y * wv.x; acc[1][1] += av.y * wv.y; acc[1][2] += av.y * wv.z; acc[1][3] += av.y * wv.w;
            acc[2][0] += av.z * wv.x; acc[2][1] += av.z * wv.y; acc[2][2] += av.z * wv.z; acc[2][3] += av.z * wv.w;
            acc[3][0] += av.w * wv.x; acc[3][1] += av.w * wv.y; acc[3][2] += av.w * wv.z; acc[3][3] += av.w * wv.w;
        }
        __syncthreads();
    }
#pragma unroll
    for (int i = 0; i < 4; i++) {
        int m = m0 + ty * 4 + i;
#pragma unroll
        for (int j = 0; j < 4; j++) {
            int n = n0 + tx * 4 + j;
            float v = acc[i][j];
            if (use_bertbias) v += d_bertbias[(m & 31) * NDJ + n];
            if (b1) v += b1[n] + b2[n];
            d_preG[(size_t)m * NDJ + n] = v;
        }
    }
}

// ---------------- LSTM step: one launch per timestep; 128 blocks = 2 dirs x 64 h-chunks ----------------
// block (d, hch) computes gates for cols {g*512 + hch*8 + hh : g<4, hh<8} over all 32 batches,
// then applies the cell update for its owned h-slice.
#define STEP_SMEM ((512 * 36 + 32 * 513 + 32 * 33) * 4)
__global__ __launch_bounds__(256) void step_kernel(
    const float* __restrict__ whh_l, int t_fwd, int parity, int layer)
{
    extern __shared__ float sh[];
    float* hT = sh;                       // [512][36] transposed h
    float* wS = sh + 512 * 36;            // [32][513] w rows for this block's cols
    float* gS = wS + 32 * 513;            // [32][33] gate exchange

    const float* h_in  = parity ? d_hB : d_hA;
    float*       h_out = parity ? d_hA : d_hB;
    float*       outbuf = layer ? d_out1 : d_out0;

    const int tid = threadIdx.x;
    const int d = blockIdx.x >> 6;
    const int hch = blockIdx.x & 63;
    const int hbase = hch * 8;
    const int t = d ? (S_ - 1 - t_fwd) : t_fwd;

    // load h (this direction) transposed into SMEM
    const float* hin = h_in + d * Bz * H_;
    for (int idx = tid * 4; idx < Bz * H_; idx += 256 * 4) {
        float4 v = *(const float4*)&hin[idx];
        int b = idx >> 9, k = idx & 511;
        hT[(k + 0) * 36 + b] = v.x;
        hT[(k + 1) * 36 + b] = v.y;
        hT[(k + 2) * 36 + b] = v.z;
        hT[(k + 3) * 36 + b] = v.w;
    }
    // load 32 W_hh rows into SMEM
    {
        int c = tid >> 3;                 // 0..31
        int g = c >> 3, hh = c & 7;
        const float* wrow = whh_l + (size_t)d * 2048 * 512 + (size_t)(g * 512 + hbase + hh) * 512;
        for (int k = (tid & 7) * 4; k < 512; k += 32) {
            float4 v = *(const float4*)&wrow[k];
            wS[c * 513 + k + 0] = v.x;
            wS[c * 513 + k + 1] = v.y;
            wS[c * 513 + k + 2] = v.z;
            wS[c * 513 + k + 3] = v.w;
        }
    }
    __syncthreads();

    // compute: thread = (col c, batch quad bq)
    const int c = tid & 31, bq = tid >> 5, b0 = bq * 4;
    float a0 = 0.f, a1 = 0.f, a2 = 0.f, a3 = 0.f;
    const float* wc = &wS[c * 513];
#pragma unroll 8
    for (int k = 0; k < 512; k++) {
        float w = wc[k];
        float4 h4 = *(const float4*)&hT[k * 36 + b0];
        a0 += w * h4.x; a1 += w * h4.y; a2 += w * h4.z; a3 += w * h4.w;
    }
    const int g = c >> 3, hh = c & 7;
    const int dj = d * 2048 + g * 512 + hbase + hh;
    const float* pg = d_preG + ((size_t)t * Bz) * NDJ + dj;
    gS[(b0 + 0) * 33 + c] = a0 + pg[(size_t)(b0 + 0) * NDJ];
    gS[(b0 + 1) * 33 + c] = a1 + pg[(size_t)(b0 + 1) * NDJ];
    gS[(b0 + 2) * 33 + c] = a2 + pg[(size_t)(b0 + 2) * NDJ];
    gS[(b0 + 3) * 33 + c] = a3 + pg[(size_t)(b0 + 3) * NDJ];
    __syncthreads();

    // cell update: thread = (b, hh2)
    {
        int b = tid >> 3, hh2 = tid & 7;
        float gi = gS[b * 33 + 0 + hh2];
        float gf = gS[b * 33 + 8 + hh2];
        float gg = gS[b * 33 + 16 + hh2];
        float go = gS[b * 33 + 24 + hh2];
        int hidx = hbase + hh2;
        size_t cix = (size_t)d * Bz * H_ + (size_t)b * H_ + hidx;
        float cp = d_cS[cix];
        float cn = sigmoidf_(gf) * cp + sigmoidf_(gi) * tanhf(gg);
        float hn = sigmoidf_(go) * tanhf(cn);
        d_cS[cix] = cn;
        h_out[cix] = hn;
        outbuf[((size_t)t * Bz + b) * (2 * H_) + d * H_ + hidx] = hn;
    }
}

// ---------------- heads: feat[t*B+b][j], j<32 pos / 32..95 morph ----------------
__global__ __launch_bounds__(256) void head_kernel(
    const float* __restrict__ wp, const float* __restrict__ bp,
    const float* __restrict__ wm, const float* __restrict__ bm)
{
    __shared__ float Ash[32][65];
    __shared__ float Wsh[64][100];
    const int tid = threadIdx.x;
    const int row0 = blockIdx.x * 32;
    const int r = tid >> 3, jq = tid & 7;
    float acc[12];
#pragma unroll
    for (int j = 0; j < 12; j++) acc[j] = 0.f;

    const float* X = (const float*)d_out1;
    for (int k0 = 0; k0 < 1024; k0 += 64) {
        for (int idx = tid; idx < 32 * 64; idx += 256) {
            int rr = idx >> 6, kk = idx & 63;
            Ash[rr][kk] = X[(size_t)(row0 + rr) * 1024 + k0 + kk];
        }
        for (int idx = tid; idx < 96 * 64; idx += 256) {
            int j = idx >> 6, kk = idx & 63;
            float v = (j < 32) ? wp[(size_t)j * 1024 + k0 + kk]
                               : wm[(size_t)(j - 32) * 1024 + k0 + kk];
            Wsh[kk][j] = v;
        }
        __syncthreads();
        for (int k = 0; k < 64; k++) {
            float a = Ash[r][k];
#pragma unroll
            for (int j = 0; j < 12; j++) acc[j] += a * Wsh[k][jq * 12 + j];
        }
        __syncthreads();
    }
#pragma unroll
    for (int j = 0; j < 12; j++) {
        int jj = jq * 12 + j;
        float bias = (jj < 32) ? bp[jj] : bm[jj - 32];
        d_feat[(size_t)(row0 + r) * 96 + jj] = acc[j] + bias;
    }
}

// ---------------- CRF log-likelihood (one block per batch elem) ----------------
template <int K>
__global__ __launch_bounds__(128) void crf_kernel(
    int off, const int* __restrict__ labels,
    const float* __restrict__ start, const float* __restrict__ trans,
    const float* __restrict__ endv, float* __restrict__ out)
{
    __shared__ float tr[K * K];
    __shared__ float al[2][K];
    __shared__ float red[128];
    const int b = blockIdx.x, tid = threadIdx.x;

    for (int i = tid; i < K * K; i += 128) tr[i] = trans[i];

    // numerator pieces (global reads; tr not yet needed)
    float local = 0.f;
    for (int t = tid; t < S_; t += 128)
        local += d_feat[((size_t)t * Bz + b) * 96 + off + labels[t * Bz + b]];
    for (int t = tid; t < S_ - 1; t += 128)
        local += trans[labels[t * Bz + b] * K + labels[(t + 1) * Bz + b]];
    red[tid] = local;
    __syncthreads();
    for (int s = 64; s > 0; s >>= 1) {
        if (tid < s) red[tid] += red[tid + s];
        __syncthreads();
    }

    // partition function (alpha recursion)
    if (tid < K) al[0][tid] = start[tid] + d_feat[((size_t)0 * Bz + b) * 96 + off + tid];
    __syncthreads();
    int cur = 0;
    for (int t = 1; t < S_; t++) {
        if (tid < K) {
            float m = -1e30f;
#pragma unroll 4
            for (int i = 0; i < K; i++) {
                float v = al[cur][i] + tr[i * K + tid];
                m = fmaxf(m, v);
            }
            float s = 0.f;
#pragma unroll 4
            for (int i = 0; i < K; i++)
                s += expf(al[cur][i] + tr[i * K + tid] - m);
            al[cur ^ 1][tid] = m + logf(s) + d_feat[((size_t)t * Bz + b) * 96 + off + tid];
        }
        __syncthreads();
        cur ^= 1;
    }
    if (tid == 0) {
        float m = -1e30f;
        for (int j = 0; j < K; j++) m = fmaxf(m, al[cur][j] + endv[j]);
        float s = 0.f;
        for (int j = 0; j < K; j++) s += expf(al[cur][j] + endv[j] - m);
        float den = m + logf(s);
        float num = red[0] + start[labels[b]] + endv[labels[(S_ - 1) * Bz + b]];
        atomicAdd(out, -(num - den));
    }
}

// ---------------- launch ----------------
extern "C" void kernel_launch(void* const* d_in, const int* in_sizes, int n_in,
                              void* d_out, int out_size)
{
    const float* src    = (const float*)d_in[0];
    const float* bert   = (const float*)d_in[1];
    const int*   labp   = (const int*)d_in[2];
    const int*   labm   = (const int*)d_in[3];
    const float* w_ih   = (const float*)d_in[4];
    const float* w_hh   = (const float*)d_in[5];
    const float* b_ih   = (const float*)d_in[6];
    const float* b_hh   = (const float*)d_in[7];
    const float* hwp    = (const float*)d_in[8];
    const float* hbp    = (const float*)d_in[9];
    const float* hwm    = (const float*)d_in[10];
    const float* hbm    = (const float*)d_in[11];
    const float* st_p   = (const float*)d_in[12];
    const float* en_p   = (const float*)d_in[13];
    const float* tr_p   = (const float*)d_in[14];
    const float* st_m   = (const float*)d_in[15];
    const float* en_m   = (const float*)d_in[16];
    const float* tr_m   = (const float*)d_in[17];
    float* out = (float*)d_out;

    cudaFuncSetAttribute(step_kernel, cudaFuncAttributeMaxDynamicSharedMemorySize, STEP_SMEM);
    cudaFuncSetAttribute(bert_bias_kernel, cudaFuncAttributeMaxDynamicSharedMemorySize, BB_SMEM);

    dim3 g64(64, 64);

    // zero h/c state and the output accumulator
    zero_kernel<<<128, 256>>>(out, 1);

    // layer 0: fold bert into per-(b,dj) bias, then K=256 GEMM on src
    bert_bias_kernel<<<64, 256, BB_SMEM>>>(bert, w_ih, b_ih, b_hh);
    gemm_nt_kernel<<<g64, 256>>>(src, 256, w_ih, 1024, 256, 1, nullptr, nullptr);
    for (int t = 0; t < S_; t++)
        step_kernel<<<128, 256, STEP_SMEM>>>(w_hh, t, t & 1, 0);

    // layer 1
    zero_kernel<<<128, 256>>>(out, 0);
    gemm_nt_kernel<<<g64, 256>>>(nullptr, 1024, w_ih + (size_t)4096 * 1024, 1024, 1024, 0,
                                 b_ih + 4096, b_hh + 4096);
    for (int t = 0; t < S_; t++)
        step_kernel<<<128, 256, STEP_SMEM>>>(w_hh + (size_t)2 * 2048 * 512, t, t & 1, 1);

    // heads + CRFs
    head_kernel<<<128, 256>>>(hwp, hbp, hwm, hbm);
    crf_kernel<NTP><<<32, 128>>>(0, labp, st_p, tr_p, en_p, out);
    crf_kernel<NTM><<<32, 128>>>(32, labm, st_m, tr_m, en_m, out);
}

// round 2
// speedup vs baseline: 1.1276x; 1.1276x over previous
#include <cuda_runtime.h>
#include <math.h>
#include <stdint.h>

typedef unsigned long long ull;

#define S_    128
#define Bz    32
#define DIN   256
#define DBERT 768
#define H_    512
#define D0_   1024
#define NDJ   4096
#define NTP   32
#define NTM   64

// ---------------- persistent device scratch ----------------
__device__ float d_preG[(size_t)NDJ * 4096];     // [dj][t*B+b]  64MB
__device__ float d_out0T[(size_t)1024 * 4096];   // [2H][S*B]    16MB
__device__ float d_out1T[(size_t)1024 * 4096];   // [2H][S*B]    16MB
__device__ float d_hbuf[2][2][512][32];          // [parity][dir][hidx][b]
__device__ float d_bertbias[Bz * NDJ];           // [b][dj]
__device__ float d_feat[(size_t)S_ * Bz * 96];   // [S*B][96]
__device__ unsigned d_bcnt[2];
__device__ volatile unsigned d_bgen[2];

__device__ __forceinline__ float sigmoidf_(float x) { return 1.f / (1.f + expf(-x)); }
__device__ __forceinline__ ull packf2(float lo, float hi) {
    ull r; asm("mov.b64 %0, {%1,%2};" : "=l"(r) : "f"(lo), "f"(hi)); return r;
}
__device__ __forceinline__ void fma2(ull& d, ull a, ull b) {
    asm("fma.rn.f32x2 %0, %1, %2, %0;" : "+l"(d) : "l"(a), "l"(b));
}
__device__ __forceinline__ float2 unpackf2(ull v) {
    float2 r; asm("mov.b64 {%0,%1}, %2;" : "=f"(r.x), "=f"(r.y) : "l"(v)); return r;
}

// ---------------- zero kernel: barrier state + output scalar ----------------
__global__ void zero_kernel(float* out, int zero_out) {
    int i = threadIdx.x;
    if (i < 2) { d_bcnt[i] = 0u; d_bgen[i] = 0u; }
    if (zero_out && i == 0) out[0] = 0.f;
}

// ---------------- bert bias: bias0[b][dj] = b_ih0[dj]+b_hh0[dj] + bert[b].W_ih0[dj,256:1024] ----
#define BB_SMEM (32 * 772 * 4)
__global__ __launch_bounds__(256) void bert_bias_kernel(
    const float* __restrict__ bert, const float* __restrict__ w_ih0,
    const float* __restrict__ b_ih0, const float* __restrict__ b_hh0)
{
    extern __shared__ float sh[];   // bert_sh[32][772]
    const int tid = threadIdx.x;
    for (int idx = tid; idx < Bz * DBERT / 4; idx += 256) {
        float4 v = ((const float4*)bert)[idx];
        int e = idx * 4;
        int b = e / DBERT, k = e % DBERT;
        *(float4*)&sh[b * 772 + k] = v;
    }
    __syncthreads();
    const int djl = tid & 63, bq = tid >> 6;
    const int dj = blockIdx.x * 64 + djl;
    const float* wrow = w_ih0 + (size_t)dj * D0_ + DIN;
    float acc[8];
#pragma unroll
    for (int i = 0; i < 8; i++) acc[i] = 0.f;
    for (int k = 0; k < DBERT; k += 4) {
        float4 w4 = *(const float4*)&wrow[k];
#pragma unroll
        for (int i = 0; i < 8; i++) {
            int b = bq * 8 + i;
            float4 h4 = *(const float4*)&sh[b * 772 + k];
            acc[i] += w4.x * h4.x + w4.y * h4.y + w4.z * h4.z + w4.w * h4.w;
        }
    }
    float bias = b_ih0[dj] + b_hh0[dj];
#pragma unroll
    for (int i = 0; i < 8; i++)
        d_bertbias[(bq * 8 + i) * NDJ + dj] = acc[i] + bias;
}

// ---------------- GEMM: d_preG[m=dj][n=t*B+b] = A[m]·B[n] (+bias) ----------------
// BT=0: B is row-major [n][k] (K-major rows). BT=1: B is [k][n] (transposed; Bp==nullptr -> d_out0T).
template<int BT>
__global__ __launch_bounds__(256) void gemm_kernel(
    const float* __restrict__ A, int lda, int K,
    const float* __restrict__ Bp, int ldb,
    int use_bb, const float* __restrict__ b1, const float* __restrict__ b2)
{
    __shared__ float Asd[16 * 132];   // A tile, m-duplicated: [k][2m]
    __shared__ float Ws[16 * 68];     // B tile: [k][n]
    const float* Bx = Bp ? Bp : (const float*)d_out0T;
    const int tid = threadIdx.x;
    const int m0 = blockIdx.y * 64, n0 = blockIdx.x * 64;
    const int lr = tid >> 2, lk = (tid & 3) * 4;
    const int kr = tid >> 4, nl = tid & 15;
    const int ty = tid >> 4, tx = tid & 15;
    ull acc[4][2];
#pragma unroll
    for (int i = 0; i < 4; i++) { acc[i][0] = 0ull; acc[i][1] = 0ull; }

    for (int k0 = 0; k0 < K; k0 += 16) {
        float4 a4 = *(const float4*)&A[(size_t)(m0 + lr) * lda + k0 + lk];
        Asd[(lk + 0) * 132 + 2 * lr] = a4.x; Asd[(lk + 0) * 132 + 2 * lr + 1] = a4.x;
        Asd[(lk + 1) * 132 + 2 * lr] = a4.y; Asd[(lk + 1) * 132 + 2 * lr + 1] = a4.y;
        Asd[(lk + 2) * 132 + 2 * lr] = a4.z; Asd[(lk + 2) * 132 + 2 * lr + 1] = a4.z;
        Asd[(lk + 3) * 132 + 2 * lr] = a4.w; Asd[(lk + 3) * 132 + 2 * lr + 1] = a4.w;
        if (!BT) {
            float4 w4 = *(const float4*)&Bx[(size_t)(n0 + lr) * ldb + k0 + lk];
            Ws[(lk + 0) * 68 + lr] = w4.x;
            Ws[(lk + 1) * 68 + lr] = w4.y;
            Ws[(lk + 2) * 68 + lr] = w4.z;
            Ws[(lk + 3) * 68 + lr] = w4.w;
        } else {
            float4 w4 = *(const float4*)&Bx[(size_t)(k0 + kr) * ldb + n0 + nl * 4];
            Ws[kr * 68 + nl * 4 + 0] = w4.x;
            Ws[kr * 68 + nl * 4 + 1] = w4.y;
            Ws[kr * 68 + nl * 4 + 2] = w4.z;
            Ws[kr * 68 + nl * 4 + 3] = w4.w;
        }
        __syncthreads();
#pragma unroll
        for (int kk = 0; kk < 16; kk++) {
            ulonglong2 adA = *(const ulonglong2*)&Asd[kk * 132 + ty * 8];
            ulonglong2 adB = *(const ulonglong2*)&Asd[kk * 132 + ty * 8 + 4];
            ulonglong2 wv  = *(const ulonglong2*)&Ws[kk * 68 + tx * 4];
            fma2(acc[0][0], adA.x, wv.x); fma2(acc[0][1], adA.x, wv.y);
            fma2(acc[1][0], adA.y, wv.x); fma2(acc[1][1], adA.y, wv.y);
            fma2(acc[2][0], adB.x, wv.x); fma2(acc[2][1], adB.x, wv.y);
            fma2(acc[3][0], adB.y, wv.x); fma2(acc[3][1], adB.y, wv.y);
        }
        __syncthreads();
    }
#pragma unroll
    for (int i = 0; i < 4; i++) {
        int m = m0 + ty * 4 + i;
        float rowbias = use_bb ? 0.f : (b1[m] + b2[m]);
#pragma unroll
        for (int p = 0; p < 2; p++) {
            float2 v = unpackf2(acc[i][p]);
            int n = n0 + tx * 4 + p * 2;
            float v0 = v.x + rowbias, v1 = v.y + rowbias;
            if (use_bb) {
                v0 += d_bertbias[(n & 31) * NDJ + m];
                v1 += d_bertbias[((n + 1) & 31) * NDJ + m];
            }
            d_preG[(size_t)m * 4096 + n]     = v0;
            d_preG[(size_t)m * 4096 + n + 1] = v1;
        }
    }
}

// ---------------- persistent BiLSTM layer kernel ----------------
// 128 blocks = 2 dirs x 64 h-chunks (8 h-indices each). One block per SM, resident.
// SMEM: wdup[512][64] (W rows duplicated), hT[512][32], red[4][32][33].
#define PSMEM ((512 * 64 + 512 * 32 + 4 * 32 * 33) * 4)
__global__ __launch_bounds__(256) void lstm_layer_kernel(
    const float* __restrict__ whh, int layer)
{
    extern __shared__ float sh[];
    float* wdup = sh;                      // [512][64]
    float* hT   = sh + 512 * 64;           // [512][32]
    float* red  = sh + 512 * 64 + 512 * 32; // [4][32][33]

    const int tid = threadIdx.x;
    const int d = blockIdx.x >> 6;
    const int hch = blockIdx.x & 63;
    const int hbase = hch * 8;
    float* outT = layer ? d_out1T : d_out0T;

    // load 32 W_hh rows, duplicated: wdup[k][2c]=[2c+1]=W[dj(c)][k]
    {
        int c = tid >> 3, kc = tid & 7;
        int g = c >> 3, hh = c & 7;
        const float* wrow = whh + ((size_t)d * 2048 + g * 512 + hbase + hh) * 512;
        for (int k = kc * 64; k < kc * 64 + 64; k += 4) {
            float4 v = *(const float4*)&wrow[k];
            wdup[(k + 0) * 64 + 2 * c] = v.x; wdup[(k + 0) * 64 + 2 * c + 1] = v.x;
            wdup[(k + 1) * 64 + 2 * c] = v.y; wdup[(k + 1) * 64 + 2 * c + 1] = v.y;
            wdup[(k + 2) * 64 + 2 * c] = v.z; wdup[(k + 2) * 64 + 2 * c + 1] = v.z;
            wdup[(k + 3) * 64 + 2 * c] = v.w; wdup[(k + 3) * 64 + 2 * c + 1] = v.w;
        }
    }
    // zero hT (h_{-1} = 0)
    {
        float4 z = {0.f, 0.f, 0.f, 0.f};
        for (int i = tid; i < 512 * 32 / 4; i += 256) ((float4*)hT)[i] = z;
    }
    __syncthreads();

    // compute-thread roles: tid = ks*64 + b8*8 + c8
    const int ks = tid >> 6, b8 = (tid >> 3) & 7, c8 = tid & 7;
    // cell-update roles: tid = hh*32 + b
    const int cu_hh = tid >> 5, cu_b = tid & 31;
    float c_reg = 0.f;

    const float* wp = wdup + c8 * 8;
    const float* hp = hT + b8 * 4;

    for (int ti = 0; ti < S_; ti++) {
        const int t = d ? (S_ - 1 - ti) : ti;

        // ---- partial gate GEMM: acc[cc][bp] over k in [ks*128, ks*128+128) ----
        ull acc[4][2];
#pragma unroll
        for (int i = 0; i < 4; i++) { acc[i][0] = 0ull; acc[i][1] = 0ull; }
        {
            const int kbeg = ks * 128;
#pragma unroll 4
            for (int k = kbeg; k < kbeg + 128; k++) {
                ulonglong2 wv0 = *(const ulonglong2*)&wp[k * 64];
                ulonglong2 wv1 = *(const ulonglong2*)&wp[k * 64 + 4];
                ulonglong2 hv  = *(const ulonglong2*)&hp[k * 32];
                fma2(acc[0][0], hv.x, wv0.x); fma2(acc[0][1], hv.y, wv0.x);
                fma2(acc[1][0], hv.x, wv0.y); fma2(acc[1][1], hv.y, wv0.y);
                fma2(acc[2][0], hv.x, wv1.x); fma2(acc[2][1], hv.y, wv1.x);
                fma2(acc[3][0], hv.x, wv1.y); fma2(acc[3][1], hv.y, wv1.y);
            }
        }
        // write partials: red[ks][b][c]
        {
            float* rp = red + ks * 1056 + (b8 * 4) * 33 + c8 * 4;
#pragma unroll
            for (int cc = 0; cc < 4; cc++) {
#pragma unroll
                for (int bp = 0; bp < 2; bp++) {
                    float2 v = unpackf2(acc[cc][bp]);
                    rp[(2 * bp + 0) * 33 + cc] = v.x;
                    rp[(2 * bp + 1) * 33 + cc] = v.y;
                }
            }
        }
        __syncthreads();

        // ---- cell update: thread (cu_b, cu_hh) ----
        {
            float g[4];
#pragma unroll
            for (int gi = 0; gi < 4; gi++) {
                int c = gi * 8 + cu_hh;
                float s = red[0 * 1056 + cu_b * 33 + c] + red[1 * 1056 + cu_b * 33 + c]
                        + red[2 * 1056 + cu_b * 33 + c] + red[3 * 1056 + cu_b * 33 + c];
                size_t dj = (size_t)d * 2048 + (size_t)gi * 512 + hbase + cu_hh;
                g[gi] = s + d_preG[dj * 4096 + t * 32 + cu_b];
            }
            float cn = sigmoidf_(g[1]) * c_reg + sigmoidf_(g[0]) * tanhf(g[2]);
            float hn = sigmoidf_(g[3]) * tanhf(cn);
            c_reg = cn;
            int hidx = hbase + cu_hh;
            d_hbuf[ti & 1][d][hidx][cu_b] = hn;
            outT[((size_t)(d * 512 + hidx)) * 4096 + t * 32 + cu_b] = hn;
        }

        // ---- per-direction grid barrier ----
        __syncthreads();
        if (tid == 0) {
            __threadfence();
            unsigned target = (unsigned)(ti + 1);
            if (atomicAdd(&d_bcnt[d], 1u) == 63u) {
                atomicExch(&d_bcnt[d], 0u);
                __threadfence();
                atomicExch((unsigned*)&d_bgen[d], target);
            } else {
                while (d_bgen[d] < target) { }
                __threadfence();
            }
        }
        __syncthreads();

        // ---- stage next h into SMEM (L2-coherent loads; layout matches hT) ----
        if (ti < S_ - 1) {
            const float4* s4 = (const float4*)&d_hbuf[ti & 1][d][0][0];
            float4* d4 = (float4*)hT;
            for (int i = tid; i < 512 * 32 / 4; i += 256) d4[i] = __ldcg(&s4[i]);
            __syncthreads();
        }
    }
}

// ---------------- heads: d_feat[t*B+b][j] from d_out1T [2H][S*B] ----------------
__global__ __launch_bounds__(256) void head_kernel(
    const float* __restrict__ wp, const float* __restrict__ bp,
    const float* __restrict__ wm, const float* __restrict__ bm)
{
    __shared__ float Ash[32][65];
    __shared__ float Wsh[64][100];
    const int tid = threadIdx.x;
    const int row0 = blockIdx.x * 32;
    const int r = tid >> 3, jq = tid & 7;
    float acc[12];
#pragma unroll
    for (int j = 0; j < 12; j++) acc[j] = 0.f;

    const float* Xt = (const float*)d_out1T;
    for (int k0 = 0; k0 < 1024; k0 += 64) {
        for (int idx = tid; idx < 32 * 64; idx += 256) {
            int kk = idx >> 5, rr = idx & 31;
            Ash[rr][kk] = Xt[(size_t)(k0 + kk) * 4096 + row0 + rr];
        }
        for (int idx = tid; idx < 96 * 64; idx += 256) {
            int j = idx >> 6, kk = idx & 63;
            float v = (j < 32) ? wp[(size_t)j * 1024 + k0 + kk]
                               : wm[(size_t)(j - 32) * 1024 + k0 + kk];
            Wsh[kk][j] = v;
        }
        __syncthreads();
        for (int k = 0; k < 64; k++) {
            float a = Ash[r][k];
#pragma unroll
            for (int j = 0; j < 12; j++) acc[j] += a * Wsh[k][jq * 12 + j];
        }
        __syncthreads();
    }
#pragma unroll
    for (int j = 0; j < 12; j++) {
        int jj = jq * 12 + j;
        float bias = (jj < 32) ? bp[jj] : bm[jj - 32];
        d_feat[(size_t)(row0 + r) * 96 + jj] = acc[j] + bias;
    }
}

// ---------------- CRF log-likelihood (one block per batch elem) ----------------
template <int K>
__global__ __launch_bounds__(128) void crf_kernel(
    int off, const int* __restrict__ labels,
    const float* __restrict__ start, const float* __restrict__ trans,
    const float* __restrict__ endv, float* __restrict__ out)
{
    __shared__ float tr[K * K];
    __shared__ float al[2][K];
    __shared__ float red[128];
    const int b = blockIdx.x, tid = threadIdx.x;

    for (int i = tid; i < K * K; i += 128) tr[i] = trans[i];

    float local = 0.f;
    for (int t = tid; t < S_; t += 128)
        local += d_feat[((size_t)t * Bz + b) * 96 + off + labels[t * Bz + b]];
    for (int t = tid; t < S_ - 1; t += 128)
        local += trans[labels[t * Bz + b] * K + labels[(t + 1) * Bz + b]];
    red[tid] = local;
    __syncthreads();
    for (int s = 64; s > 0; s >>= 1) {
        if (tid < s) red[tid] += red[tid + s];
        __syncthreads();
    }

    if (tid < K) al[0][tid] = start[tid] + d_feat[((size_t)0 * Bz + b) * 96 + off + tid];
    __syncthreads();
    int cur = 0;
    for (int t = 1; t < S_; t++) {
        if (tid < K) {
            float m = -1e30f;
#pragma unroll 4
            for (int i = 0; i < K; i++) {
                float v = al[cur][i] + tr[i * K + tid];
                m = fmaxf(m, v);
            }
            float s = 0.f;
#pragma unroll 4
            for (int i = 0; i < K; i++)
                s += expf(al[cur][i] + tr[i * K + tid] - m);
            al[cur ^ 1][tid] = m + logf(s) + d_feat[((size_t)t * Bz + b) * 96 + off + tid];
        }
        __syncthreads();
        cur ^= 1;
    }
    if (tid == 0) {
        float m = -1e30f;
        for (int j = 0; j < K; j++) m = fmaxf(m, al[cur][j] + endv[j]);
        float s = 0.f;
        for (int j = 0; j < K; j++) s += expf(al[cur][j] + endv[j] - m);
        float den = m + logf(s);
        float num = red[0] + start[labels[b]] + endv[labels[(S_ - 1) * Bz + b]];
        atomicAdd(out, -(num - den));
    }
}

// ---------------- launch ----------------
extern "C" void kernel_launch(void* const* d_in, const int* in_sizes, int n_in,
                              void* d_out, int out_size)
{
    const float* src  = (const float*)d_in[0];
    const float* bert = (const float*)d_in[1];
    const int*   labp = (const int*)d_in[2];
    const int*   labm = (const int*)d_in[3];
    const float* w_ih = (const float*)d_in[4];
    const float* w_hh = (const float*)d_in[5];
    const float* b_ih = (const float*)d_in[6];
    const float* b_hh = (const float*)d_in[7];
    const float* hwp  = (const float*)d_in[8];
    const float* hbp  = (const float*)d_in[9];
    const float* hwm  = (const float*)d_in[10];
    const float* hbm  = (const float*)d_in[11];
    const float* st_p = (const float*)d_in[12];
    const float* en_p = (const float*)d_in[13];
    const float* tr_p = (const float*)d_in[14];
    const float* st_m = (const float*)d_in[15];
    const float* en_m = (const float*)d_in[16];
    const float* tr_m = (const float*)d_in[17];
    float* out = (float*)d_out;

    cudaFuncSetAttribute(lstm_layer_kernel, cudaFuncAttributeMaxDynamicSharedMemorySize, PSMEM);
    cudaFuncSetAttribute(bert_bias_kernel, cudaFuncAttributeMaxDynamicSharedMemorySize, BB_SMEM);

    dim3 g64(64, 64);

    // layer 0
    zero_kernel<<<1, 32>>>(out, 1);
    bert_bias_kernel<<<64, 256, BB_SMEM>>>(bert, w_ih, b_ih, b_hh);
    gemm_kernel<0><<<g64, 256>>>(w_ih, 1024, 256, src, 256, 1, nullptr, nullptr);
    lstm_layer_kernel<<<128, 256, PSMEM>>>(w_hh, 0);

    // layer 1
    zero_kernel<<<1, 32>>>(out, 0);
    gemm_kernel<1><<<g64, 256>>>(w_ih + (size_t)4096 * 1024, 1024, 1024,
                                 nullptr, 4096, 0, b_ih + 4096, b_hh + 4096);
    lstm_layer_kernel<<<128, 256, PSMEM>>>(w_hh + (size_t)2 * 2048 * 512, 1);

    // heads + CRFs
    head_kernel<<<128, 256>>>(hwp, hbp, hwm, hbm);
    crf_kernel<NTP><<<32, 128>>>(0, labp, st_p, tr_p, en_p, out);
    crf_kernel<NTM><<<32, 128>>>(32, labm, st_m, tr_m, en_m, out);
}

// round 3
// speedup vs baseline: 1.2210x; 1.0828x over previous
#include <cuda_runtime.h>
#include <math.h>
#include <stdint.h>

typedef unsigned long long ull;

#define S_    128
#define Bz    32
#define DIN   256
#define DBERT 768
#define H_    512
#define D0_   1024
#define NDJ   4096
#define NTP   32
#define NTM   64

// ---------------- persistent device scratch ----------------
__device__ float d_preG[(size_t)NDJ * 4096];     // [dj][t*B+b]  64MB
__device__ float d_out0T[(size_t)1024 * 4096];   // [2H][S*B]
__device__ float d_out1T[(size_t)1024 * 4096];   // [2H][S*B]
__device__ float d_hbuf[2][2][512][32];          // [parity][dir][hidx][b]
__device__ float d_bertbias[NDJ * Bz];           // [dj][b]
__device__ float d_feat[(size_t)S_ * Bz * 96];   // [S*B][96]
__device__ unsigned d_bcnt[4];
__device__ volatile unsigned d_bgen[4];

__device__ __forceinline__ float sigmoidf_(float x) { return 1.f / (1.f + expf(-x)); }
__device__ __forceinline__ void fma2(ull& d, ull a, ull b) {
    asm("fma.rn.f32x2 %0, %1, %2, %0;" : "+l"(d) : "l"(a), "l"(b));
}
__device__ __forceinline__ float2 unpackf2(ull v) {
    float2 r; asm("mov.b64 {%0,%1}, %2;" : "=f"(r.x), "=f"(r.y) : "l"(v)); return r;
}

// ---------------- zero kernel: barrier state + output scalar ----------------
__global__ void zero_kernel(float* out) {
    int i = threadIdx.x;
    if (i < 4) { d_bcnt[i] = 0u; d_bgen[i] = 0u; }
    if (i == 0) out[0] = 0.f;
}

// ---------------- bert bias: bias0[dj][b] = b_ih0[dj]+b_hh0[dj] + bert[b].W_ih0[dj,256:1024] ----
#define BB_SMEM (32 * 772 * 4)
__global__ __launch_bounds__(256) void bert_bias_kernel(
    const float* __restrict__ bert, const float* __restrict__ w_ih0,
    const float* __restrict__ b_ih0, const float* __restrict__ b_hh0)
{
    extern __shared__ float sh[];   // bert_sh[32][772]
    const int tid = threadIdx.x;
    for (int idx = tid; idx < Bz * DBERT / 4; idx += 256) {
        float4 v = ((const float4*)bert)[idx];
        int e = idx * 4;
        int b = e / DBERT, k = e % DBERT;
        *(float4*)&sh[b * 772 + k] = v;
    }
    __syncthreads();
    const int djl = tid & 63, bq = tid >> 6;
    const int dj = blockIdx.x * 64 + djl;
    const float* wrow = w_ih0 + (size_t)dj * D0_ + DIN;
    float acc[8];
#pragma unroll
    for (int i = 0; i < 8; i++) acc[i] = 0.f;
    for (int k = 0; k < DBERT; k += 4) {
        float4 w4 = *(const float4*)&wrow[k];
#pragma unroll
        for (int i = 0; i < 8; i++) {
            int b = bq * 8 + i;
            float4 h4 = *(const float4*)&sh[b * 772 + k];
            acc[i] += w4.x * h4.x + w4.y * h4.y + w4.z * h4.z + w4.w * h4.w;
        }
    }
    float bias = b_ih0[dj] + b_hh0[dj];
#pragma unroll
    for (int i = 0; i < 8; i++)
        d_bertbias[(size_t)dj * 32 + bq * 8 + i] = acc[i] + bias;
}

// ---------------- GEMM v2: d_preG[m=dj][n=t*B+b] = A[m]·B[n] (+bias) ----------------
// 128x128 tile, 256 threads, double-buffered smem, 1 sync per 16-k tile.
// BT=0: B row-major [n][k]. BT=1: B is [k][n] (Bp==nullptr -> d_out0T).
#define GEMM_SMEM ((2 * 16 * 264 + 2 * 16 * 132) * 4)
template<int BT>
__global__ __launch_bounds__(256, 2) void gemm_kernel(
    const float* __restrict__ A, int lda, int K,
    const float* __restrict__ Bp, int ldb,
    int use_bb, const float* __restrict__ b1, const float* __restrict__ b2)
{
    extern __shared__ float sh[];
    float* AsdBase = sh;                 // [2][16][264] duplicated A
    float* WsBase  = sh + 2 * 16 * 264;  // [2][16][132]
    const float* Bx = Bp ? Bp : (const float*)d_out0T;
    const int tid = threadIdx.x;
    const int m0 = blockIdx.y * 128, n0 = blockIdx.x * 128;

    // load roles
    const int am = tid >> 1, ak = (tid & 1) * 8;          // A: row am, k-offsets ak..ak+7
    const int bk = tid >> 4, bn = (tid & 15) * 8;         // B (BT=1)
    const int cn = tid >> 1, ck = (tid & 1) * 8;          // B (BT=0)
    // compute roles
    const int ty = tid >> 4, tx = tid & 15;               // m-group ty*8, n-group tx*8

    ull acc[8][4];
#pragma unroll
    for (int i = 0; i < 8; i++)
#pragma unroll
        for (int j = 0; j < 4; j++) acc[i][j] = 0ull;

    float4 ra0, ra1, rb0, rb1;
    const int NT = K / 16;

    // ---- prologue: load tile 0 into regs ----
    {
        const float* ap = &A[(size_t)(m0 + am) * lda + ak];
        ra0 = *(const float4*)ap; ra1 = *(const float4*)(ap + 4);
        if (BT) {
            const float* bp = &Bx[(size_t)bk * ldb + n0 + bn];
            rb0 = *(const float4*)bp; rb1 = *(const float4*)(bp + 4);
        } else {
            const float* bp = &Bx[(size_t)(n0 + cn) * ldb + ck];
            rb0 = *(const float4*)bp; rb1 = *(const float4*)(bp + 4);
        }
    }

    int p = 0;
    // ---- store tile 0 ----
    {
        float* Asd = AsdBase + p * (16 * 264);
        float* Ws  = WsBase  + p * (16 * 132);
        float av[8] = {ra0.x, ra0.y, ra0.z, ra0.w, ra1.x, ra1.y, ra1.z, ra1.w};
#pragma unroll
        for (int i = 0; i < 8; i++) {
            float2 dd = make_float2(av[i], av[i]);
            *(float2*)&Asd[(ak + i) * 264 + 2 * am] = dd;
        }
        if (BT) {
            *(float4*)&Ws[bk * 132 + bn] = rb0;
            *(float4*)&Ws[bk * 132 + bn + 4] = rb1;
        } else {
            float bv[8] = {rb0.x, rb0.y, rb0.z, rb0.w, rb1.x, rb1.y, rb1.z, rb1.w};
#pragma unroll
            for (int i = 0; i < 8; i++) Ws[(ck + i) * 132 + cn] = bv[i];
        }
    }
    __syncthreads();

    for (int kt = 0; kt < NT; kt++) {
        // prefetch next tile into regs
        if (kt + 1 < NT) {
            int k0 = (kt + 1) * 16;
            const float* ap = &A[(size_t)(m0 + am) * lda + k0 + ak];
            ra0 = *(const float4*)ap; ra1 = *(const float4*)(ap + 4);
            if (BT) {
                const float* bp = &Bx[(size_t)(k0 + bk) * ldb + n0 + bn];
                rb0 = *(const float4*)bp; rb1 = *(const float4*)(bp + 4);
            } else {
                const float* bp = &Bx[(size_t)(n0 + cn) * ldb + k0 + ck];
                rb0 = *(const float4*)bp; rb1 = *(const float4*)(bp + 4);
            }
        }
        // compute current tile from buffer p
        {
            const float* Asd = AsdBase + p * (16 * 264);
            const float* Ws  = WsBase  + p * (16 * 132);
#pragma unroll
            for (int kk = 0; kk < 16; kk++) {
                const float* ap = &Asd[kk * 264 + ty * 16];
                ulonglong2 a01 = *(const ulonglong2*)(ap);
                ulonglong2 a23 = *(const ulonglong2*)(ap + 4);
                ulonglong2 a45 = *(const ulonglong2*)(ap + 8);
                ulonglong2 a67 = *(const ulonglong2*)(ap + 12);
                const float* wp = &Ws[kk * 132 + tx * 8];
                ulonglong2 w01 = *(const ulonglong2*)(wp);
                ulonglong2 w23 = *(const ulonglong2*)(wp + 4);
                fma2(acc[0][0], a01.x, w01.x); fma2(acc[0][1], a01.x, w01.y);
                fma2(acc[0][2], a01.x, w23.x); fma2(acc[0][3], a01.x, w23.y);
                fma2(acc[1][0], a01.y, w01.x); fma2(acc[1][1], a01.y, w01.y);
                fma2(acc[1][2], a01.y, w23.x); fma2(acc[1][3], a01.y, w23.y);
                fma2(acc[2][0], a23.x, w01.x); fma2(acc[2][1], a23.x, w01.y);
                fma2(acc[2][2], a23.x, w23.x); fma2(acc[2][3], a23.x, w23.y);
                fma2(acc[3][0], a23.y, w01.x); fma2(acc[3][1], a23.y, w01.y);
                fma2(acc[3][2], a23.y, w23.x); fma2(acc[3][3], a23.y, w23.y);
                fma2(acc[4][0], a45.x, w01.x); fma2(acc[4][1], a45.x, w01.y);
                fma2(acc[4][2], a45.x, w23.x); fma2(acc[4][3], a45.x, w23.y);
                fma2(acc[5][0], a45.y, w01.x); fma2(acc[5][1], a45.y, w01.y);
                fma2(acc[5][2], a45.y, w23.x); fma2(acc[5][3], a45.y, w23.y);
                fma2(acc[6][0], a67.x, w01.x); fma2(acc[6][1], a67.x, w01.y);
                fma2(acc[6][2], a67.x, w23.x); fma2(acc[6][3], a67.x, w23.y);
                fma2(acc[7][0], a67.y, w01.x); fma2(acc[7][1], a67.y, w01.y);
                fma2(acc[7][2], a67.y, w23.x); fma2(acc[7][3], a67.y, w23.y);
            }
        }
        // stash next tile into alternate buffer
        if (kt + 1 < NT) {
            float* Asd = AsdBase + (p ^ 1) * (16 * 264);
            float* Ws  = WsBase  + (p ^ 1) * (16 * 132);
            float av[8] = {ra0.x, ra0.y, ra0.z, ra0.w, ra1.x, ra1.y, ra1.z, ra1.w};
#pragma unroll
            for (int i = 0; i < 8; i++) {
                float2 dd = make_float2(av[i], av[i]);
                *(float2*)&Asd[(ak + i) * 264 + 2 * am] = dd;
            }
            if (BT) {
                *(float4*)&Ws[bk * 132 + bn] = rb0;
                *(float4*)&Ws[bk * 132 + bn + 4] = rb1;
            } else {
                float bv[8] = {rb0.x, rb0.y, rb0.z, rb0.w, rb1.x, rb1.y, rb1.z, rb1.w};
#pragma unroll
                for (int i = 0; i < 8; i++) Ws[(ck + i) * 132 + cn] = bv[i];
            }
        }
        __syncthreads();
        p ^= 1;
    }

    // ---- epilogue ----
#pragma unroll
    for (int i = 0; i < 8; i++) {
        int m = m0 + ty * 8 + i;
        float rowbias = use_bb ? 0.f : (b1[m] + b2[m]);
        float4 o0, o1;
        float2 v0 = unpackf2(acc[i][0]);
        float2 v1 = unpackf2(acc[i][1]);
        float2 v2 = unpackf2(acc[i][2]);
        float2 v3 = unpackf2(acc[i][3]);
        o0 = make_float4(v0.x, v0.y, v1.x, v1.y);
        o1 = make_float4(v2.x, v2.y, v3.x, v3.y);
        if (use_bb) {
            int bb = (tx * 8) & 31;
            float4 c0 = *(const float4*)&d_bertbias[(size_t)m * 32 + bb];
            float4 c1 = *(const float4*)&d_bertbias[(size_t)m * 32 + bb + 4];
            o0.x += c0.x; o0.y += c0.y; o0.z += c0.z; o0.w += c0.w;
            o1.x += c1.x; o1.y += c1.y; o1.z += c1.z; o1.w += c1.w;
        } else {
            o0.x += rowbias; o0.y += rowbias; o0.z += rowbias; o0.w += rowbias;
            o1.x += rowbias; o1.y += rowbias; o1.z += rowbias; o1.w += rowbias;
        }
        float* dst = &d_preG[(size_t)m * 4096 + n0 + tx * 8];
        *(float4*)dst = o0;
        *(float4*)(dst + 4) = o1;
    }
}

// ---------------- persistent BiLSTM layer kernel ----------------
#define PSMEM ((512 * 64 + 512 * 32 + 4 * 32 * 33) * 4)
__global__ __launch_bounds__(256) void lstm_layer_kernel(
    const float* __restrict__ whh, int layer)
{
    extern __shared__ float sh[];
    float* wdup = sh;                        // [512][64]
    float* hT   = sh + 512 * 64;             // [512][32]
    float* red  = sh + 512 * 64 + 512 * 32;  // [4][32][33]

    const int tid = threadIdx.x;
    const int d = blockIdx.x >> 6;
    const int hch = blockIdx.x & 63;
    const int hbase = hch * 8;
    const int bslot = layer * 2 + d;
    float* outT = layer ? d_out1T : d_out0T;

    // load 32 W_hh rows, duplicated
    {
        int c = tid >> 3, kc = tid & 7;
        int g = c >> 3, hh = c & 7;
        const float* wrow = whh + ((size_t)d * 2048 + g * 512 + hbase + hh) * 512;
        for (int k = kc * 64; k < kc * 64 + 64; k += 4) {
            float4 v = *(const float4*)&wrow[k];
            wdup[(k + 0) * 64 + 2 * c] = v.x; wdup[(k + 0) * 64 + 2 * c + 1] = v.x;
            wdup[(k + 1) * 64 + 2 * c] = v.y; wdup[(k + 1) * 64 + 2 * c + 1] = v.y;
            wdup[(k + 2) * 64 + 2 * c] = v.z; wdup[(k + 2) * 64 + 2 * c + 1] = v.z;
            wdup[(k + 3) * 64 + 2 * c] = v.w; wdup[(k + 3) * 64 + 2 * c + 1] = v.w;
        }
    }
    {
        float4 z = {0.f, 0.f, 0.f, 0.f};
        for (int i = tid; i < 512 * 32 / 4; i += 256) ((float4*)hT)[i] = z;
    }
    __syncthreads();

    const int ks = tid >> 6, b8 = (tid >> 3) & 7, c8 = tid & 7;
    const int cu_hh = tid >> 5, cu_b = tid & 31;
    float c_reg = 0.f;

    const float* wp = wdup + c8 * 8;
    const float* hp = hT + b8 * 4;

    for (int ti = 0; ti < S_; ti++) {
        const int t = d ? (S_ - 1 - ti) : ti;

        // prefetch gate pre-activations (consumed after the gemm + reduction)
        float pg[4];
#pragma unroll
        for (int gi = 0; gi < 4; gi++) {
            size_t dj = (size_t)d * 2048 + (size_t)gi * 512 + hbase + cu_hh;
            pg[gi] = __ldcg(&d_preG[dj * 4096 + t * 32 + cu_b]);
        }

        // ---- partial gate GEMM ----
        ull acc[4][2];
#pragma unroll
        for (int i = 0; i < 4; i++) { acc[i][0] = 0ull; acc[i][1] = 0ull; }
        {
            const int kbeg = ks * 128;
#pragma unroll 4
            for (int k = kbeg; k < kbeg + 128; k++) {
                ulonglong2 wv0 = *(const ulonglong2*)&wp[k * 64];
                ulonglong2 wv1 = *(const ulonglong2*)&wp[k * 64 + 4];
                ulonglong2 hv  = *(const ulonglong2*)&hp[k * 32];
                fma2(acc[0][0], hv.x, wv0.x); fma2(acc[0][1], hv.y, wv0.x);
                fma2(acc[1][0], hv.x, wv0.y); fma2(acc[1][1], hv.y, wv0.y);
                fma2(acc[2][0], hv.x, wv1.x); fma2(acc[2][1], hv.y, wv1.x);
                fma2(acc[3][0], hv.x, wv1.y); fma2(acc[3][1], hv.y, wv1.y);
            }
        }
        {
            float* rp = red + ks * 1056 + (b8 * 4) * 33 + c8 * 4;
#pragma unroll
            for (int cc = 0; cc < 4; cc++) {
#pragma unroll
                for (int bp = 0; bp < 2; bp++) {
                    float2 v = unpackf2(acc[cc][bp]);
                    rp[(2 * bp + 0) * 33 + cc] = v.x;
                    rp[(2 * bp + 1) * 33 + cc] = v.y;
                }
            }
        }
        __syncthreads();

        // ---- cell update ----
        {
            float g[4];
#pragma unroll
            for (int gi = 0; gi < 4; gi++) {
                int c = gi * 8 + cu_hh;
                float s = red[0 * 1056 + cu_b * 33 + c] + red[1 * 1056 + cu_b * 33 + c]
                        + red[2 * 1056 + cu_b * 33 + c] + red[3 * 1056 + cu_b * 33 + c];
                g[gi] = s + pg[gi];
            }
            float cn = sigmoidf_(g[1]) * c_reg + sigmoidf_(g[0]) * tanhf(g[2]);
            float hn = sigmoidf_(g[3]) * tanhf(cn);
            c_reg = cn;
            int hidx = hbase + cu_hh;
            d_hbuf[ti & 1][d][hidx][cu_b] = hn;
            outT[((size_t)(d * 512 + hidx)) * 4096 + t * 32 + cu_b] = hn;
        }

        // ---- per-direction grid barrier ----
        __syncthreads();
        if (tid == 0) {
            __threadfence();
            unsigned target = (unsigned)(ti + 1);
            if (atomicAdd(&d_bcnt[bslot], 1u) == 63u) {
                atomicExch(&d_bcnt[bslot], 0u);
                __threadfence();
                atomicExch((unsigned*)&d_bgen[bslot], target);
            } else {
                while (d_bgen[bslot] < target) { }
                __threadfence();
            }
        }
        __syncthreads();

        // ---- stage next h into SMEM ----
        if (ti < S_ - 1) {
            const float4* s4 = (const float4*)&d_hbuf[ti & 1][d][0][0];
            float4* d4 = (float4*)hT;
            for (int i = tid; i < 512 * 32 / 4; i += 256) d4[i] = __ldcg(&s4[i]);
            __syncthreads();
        }
    }
}

// ---------------- heads ----------------
__global__ __launch_bounds__(256) void head_kernel(
    const float* __restrict__ wp, const float* __restrict__ bp,
    const float* __restrict__ wm, const float* __restrict__ bm)
{
    __shared__ float Ash[32][65];
    __shared__ float Wsh[64][100];
    const int tid = threadIdx.x;
    const int row0 = blockIdx.x * 32;
    const int r = tid >> 3, jq = tid & 7;
    float acc[12];
#pragma unroll
    for (int j = 0; j < 12; j++) acc[j] = 0.f;

    const float* Xt = (const float*)d_out1T;
    for (int k0 = 0; k0 < 1024; k0 += 64) {
        for (int idx = tid; idx < 32 * 64; idx += 256) {
            int kk = idx >> 5, rr = idx & 31;
            Ash[rr][kk] = Xt[(size_t)(k0 + kk) * 4096 + row0 + rr];
        }
        for (int idx = tid; idx < 96 * 64; idx += 256) {
            int j = idx >> 6, kk = idx & 63;
            float v = (j < 32) ? wp[(size_t)j * 1024 + k0 + kk]
                               : wm[(size_t)(j - 32) * 1024 + k0 + kk];
            Wsh[kk][j] = v;
        }
        __syncthreads();
        for (int k = 0; k < 64; k++) {
            float a = Ash[r][k];
#pragma unroll
            for (int j = 0; j < 12; j++) acc[j] += a * Wsh[k][jq * 12 + j];
        }
        __syncthreads();
    }
#pragma unroll
    for (int j = 0; j < 12; j++) {
        int jj = jq * 12 + j;
        float bias = (jj < 32) ? bp[jj] : bm[jj - 32];
        d_feat[(size_t)(row0 + r) * 96 + jj] = acc[j] + bias;
    }
}

// ---------------- CRF ----------------
template <int K>
__global__ __launch_bounds__(128) void crf_kernel(
    int off, const int* __restrict__ labels,
    const float* __restrict__ start, const float* __restrict__ trans,
    const float* __restrict__ endv, float* __restrict__ out)
{
    __shared__ float tr[K * K];
    __shared__ float al[2][K];
    __shared__ float red[128];
    const int b = blockIdx.x, tid = threadIdx.x;

    for (int i = tid; i < K * K; i += 128) tr[i] = trans[i];

    float local = 0.f;
    for (int t = tid; t < S_; t += 128)
        local += d_feat[((size_t)t * Bz + b) * 96 + off + labels[t * Bz + b]];
    for (int t = tid; t < S_ - 1; t += 128)
        local += trans[labels[t * Bz + b] * K + labels[(t + 1) * Bz + b]];
    red[tid] = local;
    __syncthreads();
    for (int s = 64; s > 0; s >>= 1) {
        if (tid < s) red[tid] += red[tid + s];
        __syncthreads();
    }

    if (tid < K) al[0][tid] = start[tid] + d_feat[((size_t)0 * Bz + b) * 96 + off + tid];
    __syncthreads();
    int cur = 0;
    for (int t = 1; t < S_; t++) {
        if (tid < K) {
            float m = -1e30f;
#pragma unroll 4
            for (int i = 0; i < K; i++) {
                float v = al[cur][i] + tr[i * K + tid];
                m = fmaxf(m, v);
            }
            float s = 0.f;
#pragma unroll 4
            for (int i = 0; i < K; i++)
                s += expf(al[cur][i] + tr[i * K + tid] - m);
            al[cur ^ 1][tid] = m + logf(s) + d_feat[((size_t)t * Bz + b) * 96 + off + tid];
        }
        __syncthreads();
        cur ^= 1;
    }
    if (tid == 0) {
        float m = -1e30f;
        for (int j = 0; j < K; j++) m = fmaxf(m, al[cur][j] + endv[j]);
        float s = 0.f;
        for (int j = 0; j < K; j++) s += expf(al[cur][j] + endv[j] - m);
        float den = m + logf(s);
        float num = red[0] + start[labels[b]] + endv[labels[(S_ - 1) * Bz + b]];
        atomicAdd(out, -(num - den));
    }
}

// ---------------- launch ----------------
extern "C" void kernel_launch(void* const* d_in, const int* in_sizes, int n_in,
                              void* d_out, int out_size)
{
    const float* src  = (const float*)d_in[0];
    const float* bert = (const float*)d_in[1];
    const int*   labp = (const int*)d_in[2];
    const int*   labm = (const int*)d_in[3];
    const float* w_ih = (const float*)d_in[4];
    const float* w_hh = (const float*)d_in[5];
    const float* b_ih = (const float*)d_in[6];
    const float* b_hh = (const float*)d_in[7];
    const float* hwp  = (const float*)d_in[8];
    const float* hbp  = (const float*)d_in[9];
    const float* hwm  = (const float*)d_in[10];
    const float* hbm  = (const float*)d_in[11];
    const float* st_p = (const float*)d_in[12];
    const float* en_p = (const float*)d_in[13];
    const float* tr_p = (const float*)d_in[14];
    const float* st_m = (const float*)d_in[15];
    const float* en_m = (const float*)d_in[16];
    const float* tr_m = (const float*)d_in[17];
    float* out = (float*)d_out;

    cudaFuncSetAttribute(lstm_layer_kernel, cudaFuncAttributeMaxDynamicSharedMemorySize, PSMEM);
    cudaFuncSetAttribute(bert_bias_kernel, cudaFuncAttributeMaxDynamicSharedMemorySize, BB_SMEM);
    cudaFuncSetAttribute(gemm_kernel<0>, cudaFuncAttributeMaxDynamicSharedMemorySize, GEMM_SMEM);
    cudaFuncSetAttribute(gemm_kernel<1>, cudaFuncAttributeMaxDynamicSharedMemorySize, GEMM_SMEM);

    dim3 g128(32, 32);

    // 0: zero barrier state (4 slots) + out
    zero_kernel<<<1, 32>>>(out);
    // 1: bert bias
    bert_bias_kernel<<<64, 256, BB_SMEM>>>(bert, w_ih, b_ih, b_hh);
    // 2: layer-0 input GEMM (K=256, bert folded into bias)
    gemm_kernel<0><<<g128, 256, GEMM_SMEM>>>(w_ih, 1024, 256, src, 256, 1, nullptr, nullptr);
    // 3: layer-0 BiLSTM
    lstm_layer_kernel<<<128, 256, PSMEM>>>(w_hh, 0);
    // 4: layer-1 input GEMM (K=1024)
    gemm_kernel<1><<<g128, 256, GEMM_SMEM>>>(w_ih + (size_t)4096 * 1024, 1024, 1024,
                                             nullptr, 4096, 0, b_ih + 4096, b_hh + 4096);
    // 5: layer-1 BiLSTM  (ncu -s 5 should land here)
    lstm_layer_kernel<<<128, 256, PSMEM>>>(w_hh + (size_t)2 * 2048 * 512, 1);
    // 6-8: heads + CRFs
    head_kernel<<<128, 256>>>(hwp, hbp, hwm, hbm);
    crf_kernel<NTP><<<32, 128>>>(0, labp, st_p, tr_p, en_p, out);
    crf_kernel<NTM><<<32, 128>>>(32, labm, st_m, tr_m, en_m, out);
}